// round 8
// baseline (speedup 1.0000x reference)
#include <cuda_runtime.h>
#include <cuda_fp16.h>
#include <math.h>

// Problem constants (fixed by the dataset)
#define NMAX   100000
#define EMAX   1000000
#define DIM    64
#define Hdim   14     // H = 2*LAT
#define PD     16     // P = (LAT+1)*R
#define LATC   7
#define OUTC   30     // 7 loc + 7 scale + 14 U + 2 m
#define SP_INV_1 0.5413248546129181f
#define CHUNK  16     // edges per quad in eagg

// ---------------- scratch (static device globals; no allocation allowed) ---
__device__ uint2  g_Y1h[NMAX * 4];    // X@W1 (fp16, padded 16 feats, pads=0)
__device__ uint2  g_Y2h[NMAX * 4];    // relu(Z1)@W2 (fp16)
__device__ float4 g_Z1[NMAX * 4];     // agg layer-1 accumulator (fp32)
__device__ float4 g_Z2[NMAX * 4];     // agg layer-2 accumulator (fp32)
__device__ int    g_cnt[NMAX + 1];    // degree histogram; [NMAX] = scan total
__device__ int    g_start[NMAX];      // bucket base offsets (disjoint)
__device__ int    g_rank[EMAX];       // within-row rank of each edge
__device__ int4   g_edge4[EMAX];      // (row, col, val_bits, 0) bucketed by row

// pack 4 fp32 -> uint2 of half2
__device__ __forceinline__ uint2 pack4h(float a, float b, float c, float d) {
    half2 lo = __floats2half2_rn(a, b);
    half2 hi = __floats2half2_rn(c, d);
    uint2 r;
    r.x = *reinterpret_cast<unsigned*>(&lo);
    r.y = *reinterpret_cast<unsigned*>(&hi);
    return r;
}
// unpack uint2(half2x2) and fma into fp32 acc
__device__ __forceinline__ void fma_h4(float4& acc, uint2 r, float v) {
    half2 lo = *reinterpret_cast<half2*>(&r.x);
    half2 hi = *reinterpret_cast<half2*>(&r.y);
    float2 f01 = __half22float2(lo);
    float2 f23 = __half22float2(hi);
    acc.x += v * f01.x; acc.y += v * f01.y;
    acc.z += v * f23.x; acc.w += v * f23.y;
}
__device__ __forceinline__ void red4(float4* addr, float4 v) {
    asm volatile("red.global.add.v4.f32 [%0], {%1,%2,%3,%4};"
                 :: "l"(addr), "f"(v.x), "f"(v.y), "f"(v.z), "f"(v.w)
                 : "memory");
}

// ---------------- K_FAT: gemm1 (blocks < gN) || histogram+rank (rest) ------
__global__ void k_fat(const float* __restrict__ X, const float* __restrict__ W1,
                      const int* __restrict__ rows, int N, int E, int gN) {
    if ((int)blockIdx.x >= gN) {
        int e = (blockIdx.x - gN) * blockDim.x + threadIdx.x;
        if (e < E) {
            int rk = atomicAdd(&g_cnt[rows[e]], 1);
            g_rank[e] = rk;
        }
        return;
    }

    __shared__ float sW[DIM * Hdim];   // 896 floats
    for (int t = threadIdx.x; t < DIM * Hdim; t += blockDim.x)
        sW[t] = W1[t];
    __syncthreads();

    int i = blockIdx.x * blockDim.x + threadIdx.x;
    if (i >= N) return;

    const float4* x4 = (const float4*)(X + (long)i * DIM);
    float acc[Hdim];
#pragma unroll
    for (int j = 0; j < Hdim; ++j) acc[j] = 0.f;

#pragma unroll
    for (int k4 = 0; k4 < DIM / 4; ++k4) {
        float4 x = x4[k4];
        const float* w = &sW[k4 * 4 * Hdim];
#pragma unroll
        for (int j = 0; j < Hdim; ++j)
            acc[j] += x.x * w[j] + x.y * w[Hdim + j]
                    + x.z * w[2 * Hdim + j] + x.w * w[3 * Hdim + j];
    }

    g_Y1h[i * 4 + 0] = pack4h(acc[0], acc[1], acc[2], acc[3]);
    g_Y1h[i * 4 + 1] = pack4h(acc[4], acc[5], acc[6], acc[7]);
    g_Y1h[i * 4 + 2] = pack4h(acc[8], acc[9], acc[10], acc[11]);
    g_Y1h[i * 4 + 3] = pack4h(acc[12], acc[13], 0.f, 0.f);
}

// ---------------- one-pass scan: disjoint bucket bases via atomic total -----
__global__ void k_scan(int N) {
    int t = threadIdx.x;
    int i = blockIdx.x * 256 + t;
    int v = (i < N) ? g_cnt[i] : 0;

    int lane = t & 31, w = t >> 5;
    int x = v;
#pragma unroll
    for (int off = 1; off < 32; off <<= 1) {
        int y = __shfl_up_sync(0xffffffffu, x, off);
        if (lane >= off) x += y;
    }

    __shared__ int wsum[8];
    __shared__ int bbase;
    if (lane == 31) wsum[w] = x;
    __syncthreads();
    if (t < 8) {
        int s = wsum[t];
#pragma unroll
        for (int off = 1; off < 8; off <<= 1) {
            int y = __shfl_up_sync(0xffu, s, off);
            if (t >= off) s += y;
        }
        wsum[t] = s;
        if (t == 7) bbase = atomicAdd(&g_cnt[NMAX], s);  // block base
    }
    __syncthreads();

    if (i < N) {
        int excl = (x - v) + ((w > 0) ? wsum[w - 1] : 0);
        g_start[i] = bbase + excl;
    }
}

// atomic-free scatter using precomputed ranks; record row in the edge
__global__ void k_fill(const int* __restrict__ rows, const int* __restrict__ cols,
                       const float* __restrict__ vals, int E) {
    int e = blockIdx.x * blockDim.x + threadIdx.x;
    if (e >= E) return;
    int r = rows[e];
    int pos = g_start[r] + g_rank[e];
    g_edge4[pos] = make_int4(r, cols[e], __float_as_int(vals[e]), 0);
}

// ---------------- K_EAGG: edge-chunk aggregation, perfectly balanced -------
// quad of lanes owns CHUNK contiguous (bucketed) edges; lane q owns feature
// chunk q (4 feats). Segment sums flushed via red.global.add.v4.f32 into Z.
__global__ void k_eagg(int E, int layer) {
    const uint2* __restrict__ src = layer ? g_Y2h : g_Y1h;
    float4* Z = layer ? g_Z2 : g_Z1;

    int t = blockIdx.x * blockDim.x + threadIdx.x;
    int quad = t >> 2, q = t & 3;
    int e0 = quad * CHUNK;
    if (e0 >= E) return;
    int e1 = min(E, e0 + CHUNK);

    int cur = -1;
    float4 acc = make_float4(0.f, 0.f, 0.f, 0.f);

    int e = e0;
    if (e + 4 <= e1) {
        // software-pipelined batches of 4
        int4 edc[4];
#pragma unroll
        for (int u = 0; u < 4; ++u) edc[u] = __ldg(&g_edge4[e + u]);

        for (;;) {
            uint2 s[4];
#pragma unroll
            for (int u = 0; u < 4; ++u)
                s[u] = __ldg(&src[(long)edc[u].y * 4 + q]);

            bool more = (e + 8 <= e1);
            int4 edn[4];
            if (more) {
#pragma unroll
                for (int u = 0; u < 4; ++u) edn[u] = __ldg(&g_edge4[e + 4 + u]);
            }

#pragma unroll
            for (int u = 0; u < 4; ++u) {
                if (edc[u].x != cur) {
                    if (cur >= 0) red4(&Z[(long)cur * 4 + q], acc);
                    cur = edc[u].x;
                    acc = make_float4(0.f, 0.f, 0.f, 0.f);
                }
                fma_h4(acc, s[u], __int_as_float(edc[u].z));
            }

            e += 4;
            if (!more) break;
#pragma unroll
            for (int u = 0; u < 4; ++u) edc[u] = edn[u];
        }
    }
    // scalar tail
    for (; e < e1; ++e) {
        int4 ed = __ldg(&g_edge4[e]);
        uint2 s = __ldg(&src[(long)ed.y * 4 + q]);
        if (ed.x != cur) {
            if (cur >= 0) red4(&Z[(long)cur * 4 + q], acc);
            cur = ed.x;
            acc = make_float4(0.f, 0.f, 0.f, 0.f);
        }
        fma_h4(acc, s, __int_as_float(ed.z));
    }
    if (cur >= 0) red4(&Z[(long)cur * 4 + q], acc);
}

// ---------------- helpers ---------------------------------------------------
__device__ __forceinline__ float ftanh(float x) {
    x = fminf(fmaxf(x, -15.f), 15.f);
    float e = __expf(2.f * x);
    return (e - 1.f) / (e + 1.f);
}
__device__ __forceinline__ float fsoftplus(float x) {
    return log1pf(__expf(x));   // input range ~[-0.46, 1.54]: safe
}

// ---------------- K_MID: Y2h = pack( relu(Z1) @ W2 ) -----------------------
__global__ void k_mid(const float* __restrict__ W2, int N) {
    __shared__ float sW[Hdim * 16];    // W2 padded to 14x16, pads = 0
    for (int t = threadIdx.x; t < Hdim * 16; t += blockDim.x) {
        int k = t >> 4, j = t & 15;
        sW[t] = (j < Hdim) ? W2[k * Hdim + j] : 0.f;
    }
    __syncthreads();

    int i = blockIdx.x * blockDim.x + threadIdx.x;
    if (i >= N) return;

    float h[Hdim];
    float4 a = g_Z1[i * 4 + 0];
    float4 b = g_Z1[i * 4 + 1];
    float4 c = g_Z1[i * 4 + 2];
    float4 d = g_Z1[i * 4 + 3];
    h[0]=fmaxf(a.x,0.f); h[1]=fmaxf(a.y,0.f); h[2]=fmaxf(a.z,0.f); h[3]=fmaxf(a.w,0.f);
    h[4]=fmaxf(b.x,0.f); h[5]=fmaxf(b.y,0.f); h[6]=fmaxf(b.z,0.f); h[7]=fmaxf(b.w,0.f);
    h[8]=fmaxf(c.x,0.f); h[9]=fmaxf(c.y,0.f); h[10]=fmaxf(c.z,0.f); h[11]=fmaxf(c.w,0.f);
    h[12]=fmaxf(d.x,0.f); h[13]=fmaxf(d.y,0.f);

    float y[16];
#pragma unroll
    for (int j = 0; j < 16; ++j) y[j] = 0.f;
#pragma unroll
    for (int k = 0; k < Hdim; ++k) {
        float hk = h[k];
#pragma unroll
        for (int j = 0; j < 16; ++j)
            y[j] += hk * sW[k * 16 + j];
    }

    g_Y2h[i * 4 + 0] = pack4h(y[0], y[1], y[2], y[3]);
    g_Y2h[i * 4 + 1] = pack4h(y[4], y[5], y[6], y[7]);
    g_Y2h[i * 4 + 2] = pack4h(y[8], y[9], y[10], y[11]);
    g_Y2h[i * 4 + 3] = pack4h(y[12], y[13], 0.f, 0.f);
}

// ---------------- K_OUT: relu(Z2) -> heads -> out ---------------------------
__global__ void k_out(const float* __restrict__ Wd1, const float* __restrict__ bd1,
                      const float* __restrict__ Wd2, const float* __restrict__ bd2,
                      float* __restrict__ out, int N) {
    __shared__ float sW1[Hdim * 16];   // Wd1 padded 14x16
    __shared__ float sW2[Hdim * 16];   // Wd2 14x16 (natural)
    __shared__ float sB1[16];
    __shared__ float sB2[16];
    for (int t = threadIdx.x; t < Hdim * 16; t += blockDim.x) {
        int k = t >> 4, j = t & 15;
        sW1[t] = (j < Hdim) ? Wd1[k * Hdim + j] : 0.f;
        sW2[t] = Wd2[k * PD + j];
    }
    if (threadIdx.x < 16) {
        sB1[threadIdx.x] = (threadIdx.x < Hdim) ? bd1[threadIdx.x] : 0.f;
        sB2[threadIdx.x] = bd2[threadIdx.x];
    }
    __syncthreads();

    int i = blockIdx.x * blockDim.x + threadIdx.x;
    if (i >= N) return;

    float h[Hdim];
    float4 a = g_Z2[i * 4 + 0];
    float4 b = g_Z2[i * 4 + 1];
    float4 c = g_Z2[i * 4 + 2];
    float4 d = g_Z2[i * 4 + 3];
    h[0]=fmaxf(a.x,0.f); h[1]=fmaxf(a.y,0.f); h[2]=fmaxf(a.z,0.f); h[3]=fmaxf(a.w,0.f);
    h[4]=fmaxf(b.x,0.f); h[5]=fmaxf(b.y,0.f); h[6]=fmaxf(b.z,0.f); h[7]=fmaxf(b.w,0.f);
    h[8]=fmaxf(c.x,0.f); h[9]=fmaxf(c.y,0.f); h[10]=fmaxf(c.z,0.f); h[11]=fmaxf(c.w,0.f);
    h[12]=fmaxf(d.x,0.f); h[13]=fmaxf(d.y,0.f);

    float pd[16], pp[16];
#pragma unroll
    for (int j = 0; j < 16; ++j) { pd[j] = sB1[j]; pp[j] = sB2[j]; }
#pragma unroll
    for (int k = 0; k < Hdim; ++k) {
        float hk = h[k];
#pragma unroll
        for (int j = 0; j < 16; ++j) {
            pd[j] += hk * sW1[k * 16 + j];
            pp[j] += hk * sW2[k * 16 + j];
        }
    }

    float* o = out + (long)i * OUTC;
#pragma unroll
    for (int j = 0; j < LATC; ++j)
        o[j] = ftanh(pd[j]);
#pragma unroll
    for (int j = 0; j < LATC; ++j)
        o[LATC + j] = fsoftplus(ftanh(pd[LATC + j]) + SP_INV_1);
#pragma unroll
    for (int j = 0; j < PD; ++j)
        o[2 * LATC + j] = ftanh(pp[j]);   // U(14) + m(2)
}

// ---------------- launch ----------------------------------------------------
extern "C" void kernel_launch(void* const* d_in, const int* in_sizes, int n_in,
                              void* d_out, int out_size) {
    const float* X    = (const float*)d_in[0];
    const int*   rows = (const int*)d_in[1];
    const int*   cols = (const int*)d_in[2];
    const float* vals = (const float*)d_in[3];
    const float* W1   = (const float*)d_in[4];
    const float* W2   = (const float*)d_in[5];
    const float* Wd1  = (const float*)d_in[6];
    const float* bd1  = (const float*)d_in[7];
    const float* Wd2  = (const float*)d_in[8];
    const float* bd2  = (const float*)d_in[9];
    float* out = (float*)d_out;

    int N = in_sizes[0] / DIM;
    int E = in_sizes[1];

    const int T = 256;
    int gN = (N + T - 1) / T;                       // node blocks
    int gE = (E + T - 1) / T;                       // edge blocks
    int nb = (N + 255) / 256;                       // scan blocks
    int nQuads = (E + CHUNK - 1) / CHUNK;
    int gQ = (nQuads * 4 + T - 1) / T;              // eagg blocks

    // zero histogram + scan total + Z accumulators
    void* p = nullptr;
    cudaGetSymbolAddress(&p, g_cnt);
    cudaMemsetAsync(p, 0, (size_t)(NMAX + 1) * sizeof(int));
    cudaGetSymbolAddress(&p, g_Z1);
    cudaMemsetAsync(p, 0, (size_t)NMAX * 4 * sizeof(float4));
    cudaGetSymbolAddress(&p, g_Z2);
    cudaMemsetAsync(p, 0, (size_t)NMAX * 4 * sizeof(float4));

    k_fat <<<gN + gE, T>>>(X, W1, rows, N, E, gN);   // gemm1 || histogram+rank
    k_scan<<<nb, 256>>>(N);
    k_fill<<<gE, T>>>(rows, cols, vals, E);
    k_eagg<<<gQ, T>>>(E, 0);
    k_mid <<<gN, T>>>(W2, N);
    k_eagg<<<gQ, T>>>(E, 1);
    k_out <<<gN, T>>>(Wd1, bd1, Wd2, bd2, out, N);
}